// round 1
// baseline (speedup 1.0000x reference)
#include <cuda_runtime.h>
#include <cuda_bf16.h>
#include <cstdint>

// OctreeMaxUnpool:
//   out[(i*8 + c)*C + k] = (indices[i*C + k] == c) ? data[nempty_idx[i]*C + k] : 0
// for i in [0, num), c in [0, 8), k in [0, C).
//
// Fast path: C % 4 == 0 (C=64 in this problem). 16 threads cover one row
// (C4 = C/4 float4 lanes). Each thread reads one float4 of the gathered data
// row and one int4 of indices, then writes 8 float4's — one per child slot —
// each store coalesced across the row's lanes (C4 * 16B contiguous bytes).
// Every output element is written exactly once; zeros are produced inline
// (no separate memset pass -> minimal HBM traffic).

#define NUM_CHILDREN 8

template <int C4>
__global__ void __launch_bounds__(256)
octree_unpool_vec_kernel(const float4* __restrict__ data,
                         const int4*  __restrict__ indices,
                         const int*   __restrict__ nempty_idx,
                         float4*      __restrict__ out,
                         int num)
{
    int gtid = blockIdx.x * blockDim.x + threadIdx.x;
    int i    = gtid / C4;          // row index
    int lane = gtid - i * C4;      // float4 lane within row
    if (i >= num) return;

    int src = __ldg(&nempty_idx[i]);
    float4 d  = __ldg(&data[(long long)src * C4 + lane]);
    int4   ix = __ldg(&indices[(long long)i * C4 + lane]);

    long long base = (long long)i * (NUM_CHILDREN * C4) + lane;
#pragma unroll
    for (int c = 0; c < NUM_CHILDREN; c++) {
        float4 o;
        o.x = (ix.x == c) ? d.x : 0.0f;
        o.y = (ix.y == c) ? d.y : 0.0f;
        o.z = (ix.z == c) ? d.z : 0.0f;
        o.w = (ix.w == c) ? d.w : 0.0f;
        out[base + (long long)c * C4] = o;
    }
}

// Generic-C vectorized kernel (runtime C4) for C % 4 == 0 but C != 64.
__global__ void __launch_bounds__(256)
octree_unpool_vec_dyn_kernel(const float4* __restrict__ data,
                             const int4*  __restrict__ indices,
                             const int*   __restrict__ nempty_idx,
                             float4*      __restrict__ out,
                             int num, int C4)
{
    int gtid = blockIdx.x * blockDim.x + threadIdx.x;
    int i    = gtid / C4;
    int lane = gtid - i * C4;
    if (i >= num) return;

    int src = __ldg(&nempty_idx[i]);
    float4 d  = __ldg(&data[(long long)src * C4 + lane]);
    int4   ix = __ldg(&indices[(long long)i * C4 + lane]);

    long long base = (long long)i * (NUM_CHILDREN * C4) + lane;
#pragma unroll
    for (int c = 0; c < NUM_CHILDREN; c++) {
        float4 o;
        o.x = (ix.x == c) ? d.x : 0.0f;
        o.y = (ix.y == c) ? d.y : 0.0f;
        o.z = (ix.z == c) ? d.z : 0.0f;
        o.w = (ix.w == c) ? d.w : 0.0f;
        out[base + (long long)c * C4] = o;
    }
}

// Scalar fallback for arbitrary C.
__global__ void __launch_bounds__(256)
octree_unpool_scalar_kernel(const float* __restrict__ data,
                            const int*   __restrict__ indices,
                            const int*   __restrict__ nempty_idx,
                            float*       __restrict__ out,
                            int num, int C)
{
    long long gtid = (long long)blockIdx.x * blockDim.x + threadIdx.x;
    long long total = (long long)num * C;
    if (gtid >= total) return;
    int i = (int)(gtid / C);
    int k = (int)(gtid - (long long)i * C);

    int src  = __ldg(&nempty_idx[i]);
    float dv = __ldg(&data[(long long)src * C + k]);
    int   ix = __ldg(&indices[(long long)i * C + k]);

    long long base = ((long long)i * NUM_CHILDREN) * C + k;
#pragma unroll
    for (int c = 0; c < NUM_CHILDREN; c++) {
        out[base + (long long)c * C] = (ix == c) ? dv : 0.0f;
    }
}

extern "C" void kernel_launch(void* const* d_in, const int* in_sizes, int n_in,
                              void* d_out, int out_size)
{
    const float* data       = (const float*)d_in[0];
    const int*   indices    = (const int*)d_in[1];
    const int*   nempty_idx = (const int*)d_in[2];
    // d_in[3] = depth (unused: gather at depth is already expressed by nempty_idx)

    float* out = (float*)d_out;

    int num = in_sizes[2];                       // number of non-empty nodes
    int C   = (num > 0) ? (in_sizes[1] / num) : 0;

    if (num <= 0 || C <= 0) return;

    if (C == 64) {
        constexpr int C4 = 16;
        long long threads = (long long)num * C4;
        int block = 256;
        int grid  = (int)((threads + block - 1) / block);
        octree_unpool_vec_kernel<C4><<<grid, block>>>(
            (const float4*)data, (const int4*)indices, nempty_idx,
            (float4*)out, num);
    } else if ((C & 3) == 0) {
        int C4 = C >> 2;
        long long threads = (long long)num * C4;
        int block = 256;
        int grid  = (int)((threads + block - 1) / block);
        octree_unpool_vec_dyn_kernel<<<grid, block>>>(
            (const float4*)data, (const int4*)indices, nempty_idx,
            (float4*)out, num, C4);
    } else {
        long long threads = (long long)num * C;
        int block = 256;
        int grid  = (int)((threads + block - 1) / block);
        octree_unpool_scalar_kernel<<<grid, block>>>(
            data, indices, nempty_idx, out, num, C);
    }
}